// round 4
// baseline (speedup 1.0000x reference)
#include <cuda_runtime.h>

#define NN  100000
#define EE  1600000
#define HD  128
#define BB  4096
#define NCTX 20

// ---------------- scratch (static device globals; no allocation) ----------------
__device__ int   g_deg[NN];
__device__ int   g_off[NN + 1];
__device__ int   g_cur[NN];
__device__ int   g_csr_src[EE];
__device__ float g_csr_w[EE];
__device__ float g_x1[NN * HD];
__device__ float g_x2[NN * HD];
__device__ float g_WT1[HD * HD];
__device__ float g_WT2[HD * HD];
__device__ float g_WcT1[384 * 128];
__device__ float g_WcT2[128 * 64];
__device__ int   g_part[256];
__device__ int   g_idx_is64;

// ---------------- dtype detection for `indices` ----------------
// If the harness kept int64, the first 23 int64 values are all in [0, NN).
// If it converted to int32, each int64 slot combines two random ints < 1e5,
// so the high word is almost surely nonzero -> at least one value >= NN.
__global__ void k_detect(const void* __restrict__ idx) {
    const long long* p = (const long long*)idx;
    int ok = 1;
    for (int i = 0; i < 23; ++i) {
        long long v = p[i];
        if (v < 0 || v >= NN) ok = 0;
    }
    g_idx_is64 = ok;
}

// ---------------- CSR build ----------------
__global__ void k_zero2() {
    int i = blockIdx.x * 256 + threadIdx.x;
    if (i < NN) { g_deg[i] = 0; g_cur[i] = 0; }
}

__global__ void k_deg(const int* __restrict__ dst) {
    int e = blockIdx.x * 256 + threadIdx.x;
    if (e < EE) {
        int d = dst[e];
        d = min(max(d, 0), NN - 1);   // free safety clamp
        atomicAdd(&g_deg[d], 1);
    }
}

__global__ void k_scan1() {
    __shared__ int s[512];
    int tid = threadIdx.x;
    int gid = blockIdx.x * 512 + tid;
    int v = (gid < NN) ? g_deg[gid] : 0;
    s[tid] = v; __syncthreads();
    for (int o = 1; o < 512; o <<= 1) {
        int t = (tid >= o) ? s[tid - o] : 0;
        __syncthreads();
        s[tid] += t;
        __syncthreads();
    }
    if (gid < NN) g_off[gid] = s[tid] - v;   // exclusive
    if (tid == 511) g_part[blockIdx.x] = s[511];
}

__global__ void k_scan2(int nb) {
    __shared__ int s[256];
    int tid = threadIdx.x;
    int v = (tid < nb) ? g_part[tid] : 0;
    s[tid] = v; __syncthreads();
    for (int o = 1; o < 256; o <<= 1) {
        int t = (tid >= o) ? s[tid - o] : 0;
        __syncthreads();
        s[tid] += t;
        __syncthreads();
    }
    if (tid < nb) g_part[tid] = s[tid] - v;  // exclusive
}

__global__ void k_scan3() {
    int gid = blockIdx.x * 512 + threadIdx.x;
    if (gid < NN) g_off[gid] += g_part[blockIdx.x];
    if (gid == 0) g_off[NN] = EE;
}

__global__ void k_csr(const int* __restrict__ src, const int* __restrict__ dst,
                      const float* __restrict__ w) {
    int e = blockIdx.x * 256 + threadIdx.x;
    if (e < EE) {
        int d = dst[e];
        int s = src[e];
        d = min(max(d, 0), NN - 1);   // free safety clamps
        s = min(max(s, 0), NN - 1);
        int slot = g_off[d] + atomicAdd(&g_cur[d], 1);
        g_csr_src[slot] = s;
        g_csr_w[slot]   = w[e];
    }
}

// ---------------- weight transposes (coalesced reads once per launch) ----------------
__global__ void k_transpose(const float* __restrict__ in, int R, int C, int which) {
    int t = blockIdx.x * 256 + threadIdx.x;
    if (t < R * C) {
        int j = t / C, k = t - j * C;
        float v = in[t];
        if      (which == 0) g_WT1 [k * R + j] = v;
        else if (which == 1) g_WT2 [k * R + j] = v;
        else if (which == 2) g_WcT1[k * R + j] = v;
        else                 g_WcT2[k * R + j] = v;
    }
}

// ---------------- fused GIN layer: gather + combine + matvec ----------------
// block = 256 threads, 32 nodes per block.
__global__ __launch_bounds__(256) void k_layer(const float* __restrict__ ndata,
                                               const float* __restrict__ b,
                                               const float* __restrict__ eps,
                                               int layer)
{
    __shared__ float Hs[32][128];
    __shared__ float WTs[32 * 128];

    const float* xin  = layer ? g_x1  : ndata;
    float*       xout = layer ? g_x2  : g_x1;
    const float* WT   = layer ? g_WT2 : g_WT1;

    int tid  = threadIdx.x;
    int warp = tid >> 5, lane = tid & 31;
    int nodeBase = blockIdx.x << 5;
    float epsv = 1.0f + eps[layer];
    const float4* x4 = (const float4*)xin;

    // phase 1: each warp computes h for 4 nodes
    for (int n = 0; n < 4; ++n) {
        int m = (warp << 2) + n;
        int node = nodeBase + m;
        int beg = g_off[node], end = g_off[node + 1];
        float ax = 0.f, ay = 0.f, az = 0.f, aw = 0.f;
        for (int base = beg; base < end; base += 32) {
            int nrem = end - base; if (nrem > 32) nrem = 32;
            int   sI = 0; float wv = 0.f;
            if (lane < nrem) { sI = g_csr_src[base + lane]; wv = g_csr_w[base + lane]; }
            #pragma unroll 4
            for (int j = 0; j < nrem; ++j) {
                int   ss = __shfl_sync(0xffffffffu, sI, j);
                float ww = __shfl_sync(0xffffffffu, wv, j);
                float4 xv = x4[ss * 32 + lane];
                ax += ww * xv.x; ay += ww * xv.y; az += ww * xv.z; aw += ww * xv.w;
            }
        }
        float inv = 1.0f / fmaxf((float)(end - beg), 1.0f);
        float4 xi = x4[node * 32 + lane];
        float4 h;
        h.x = epsv * xi.x + ax * inv;
        h.y = epsv * xi.y + ay * inv;
        h.z = epsv * xi.z + az * inv;
        h.w = epsv * xi.w + aw * inv;
        *(float4*)&Hs[m][lane << 2] = h;
    }

    // phase 2: Out[32][128] = H[32][128] @ W^T via WT[k][j], k-tiled through smem
    int jg = tid & 31;      // j tile
    int mg = tid >> 5;      // m tile
    float acc[4][4];
    #pragma unroll
    for (int a = 0; a < 4; ++a)
        #pragma unroll
        for (int c = 0; c < 4; ++c) acc[a][c] = 0.f;

    for (int kt = 0; kt < 128; kt += 32) {
        __syncthreads();
        const float4* wsrc = (const float4*)(WT + kt * 128);
        float4* wdst = (float4*)WTs;
        #pragma unroll
        for (int i = 0; i < 4; ++i)
            wdst[tid + i * 256] = wsrc[tid + i * 256];
        __syncthreads();
        #pragma unroll 4
        for (int kk = 0; kk < 32; ++kk) {
            float4 wv = *(const float4*)&WTs[kk * 128 + (jg << 2)];
            float h0 = Hs[(mg << 2) + 0][kt + kk];
            float h1 = Hs[(mg << 2) + 1][kt + kk];
            float h2 = Hs[(mg << 2) + 2][kt + kk];
            float h3 = Hs[(mg << 2) + 3][kt + kk];
            acc[0][0] += h0 * wv.x; acc[0][1] += h0 * wv.y; acc[0][2] += h0 * wv.z; acc[0][3] += h0 * wv.w;
            acc[1][0] += h1 * wv.x; acc[1][1] += h1 * wv.y; acc[1][2] += h1 * wv.z; acc[1][3] += h1 * wv.w;
            acc[2][0] += h2 * wv.x; acc[2][1] += h2 * wv.y; acc[2][2] += h2 * wv.z; acc[2][3] += h2 * wv.w;
            acc[3][0] += h3 * wv.x; acc[3][1] += h3 * wv.y; acc[3][2] += h3 * wv.z; acc[3][3] += h3 * wv.w;
        }
    }

    float4 bv = ((const float4*)b)[jg];
    int relu_f = (layer == 0);
    #pragma unroll
    for (int n = 0; n < 4; ++n) {
        int node = nodeBase + (mg << 2) + n;
        float4 o;
        o.x = acc[n][0] + bv.x;
        o.y = acc[n][1] + bv.y;
        o.z = acc[n][2] + bv.z;
        o.w = acc[n][3] + bv.w;
        if (relu_f) {
            o.x = fmaxf(o.x, 0.f); o.y = fmaxf(o.y, 0.f);
            o.z = fmaxf(o.z, 0.f); o.w = fmaxf(o.w, 0.f);
        }
        if (layer == 1 && node == 0) { o.x = 0.f; o.y = 0.f; o.z = 0.f; o.w = 0.f; }
        *(float4*)(xout + node * 128 + (jg << 2)) = o;
    }
}

// ---------------- head MLP: 8 rows per block, dual-dtype index gather ----------------
__global__ __launch_bounds__(256) void k_head(const void* __restrict__ idxp,
                                              const float* __restrict__ bc1,
                                              const float* __restrict__ bc2,
                                              const float* __restrict__ wc3,
                                              const float* __restrict__ bc3,
                                              float* __restrict__ out)
{
    __shared__ float fs [8][384];
    __shared__ float y1s[8][128];
    __shared__ float y2s[8][64];
    int tid = threadIdx.x, warp = tid >> 5, lane = tid & 31;
    int rowBase = blockIdx.x << 3;

    // gather: warp r -> row rowBase+r
    {
        int row = rowBase + warp;
        int i1, i2, cnt = 0;
        int ctxi[NCTX];
        if (g_idx_is64) {
            const long long* ip = (const long long*)idxp + (long long)row * 23;
            i1 = (int)ip[0];
            i2 = (int)ip[1];
            #pragma unroll
            for (int t = 0; t < NCTX; ++t) {
                long long cl = ip[3 + t];
                int ci = (int)cl;
                ctxi[t] = min(max(ci, 0), NN - 1);
                if (cl > 0) cnt++;
            }
        } else {
            const int* ip = (const int*)idxp + row * 23;
            i1 = ip[0];
            i2 = ip[1];
            #pragma unroll
            for (int t = 0; t < NCTX; ++t) {
                int ci = ip[3 + t];
                ctxi[t] = min(max(ci, 0), NN - 1);
                if (ci > 0) cnt++;
            }
        }
        i1 = min(max(i1, 0), NN - 1);
        i2 = min(max(i2, 0), NN - 1);

        const float4* x4 = (const float4*)g_x2;
        float4 a = x4[i1 * 32 + lane];
        float4 c = x4[i2 * 32 + lane];
        *(float4*)&fs[warp][lane << 2]         = a;
        *(float4*)&fs[warp][128 + (lane << 2)] = c;
        float sx = 0.f, sy = 0.f, sz = 0.f, sw = 0.f;
        #pragma unroll 4
        for (int t = 0; t < NCTX; ++t) {
            float4 xv = x4[ctxi[t] * 32 + lane];
            sx += xv.x; sy += xv.y; sz += xv.z; sw += xv.w;
        }
        float inv = 1.0f / (float)(cnt > 0 ? cnt : 1);
        float4 cv; cv.x = sx * inv; cv.y = sy * inv; cv.z = sz * inv; cv.w = sw * inv;
        *(float4*)&fs[warp][256 + (lane << 2)] = cv;
    }
    __syncthreads();

    // y1 = relu(f @ Wc1^T + bc1)
    {
        int j  = tid & 127;
        int r0 = (tid >> 7) << 2;
        float a0 = bc1[j], a1 = a0, a2 = a0, a3 = a0;
        #pragma unroll 4
        for (int k = 0; k < 384; ++k) {
            float wv = g_WcT1[k * 128 + j];
            a0 += fs[r0 + 0][k] * wv;
            a1 += fs[r0 + 1][k] * wv;
            a2 += fs[r0 + 2][k] * wv;
            a3 += fs[r0 + 3][k] * wv;
        }
        y1s[r0 + 0][j] = fmaxf(a0, 0.f);
        y1s[r0 + 1][j] = fmaxf(a1, 0.f);
        y1s[r0 + 2][j] = fmaxf(a2, 0.f);
        y1s[r0 + 3][j] = fmaxf(a3, 0.f);
    }
    __syncthreads();

    // y2 = relu(y1 @ Wc2^T + bc2)
    {
        int j  = tid & 63;
        int r0 = (tid >> 6) << 1;
        float a0 = bc2[j], a1 = a0;
        #pragma unroll 4
        for (int k = 0; k < 128; ++k) {
            float wv = g_WcT2[k * 64 + j];
            a0 += y1s[r0 + 0][k] * wv;
            a1 += y1s[r0 + 1][k] * wv;
        }
        y2s[r0 + 0][j] = fmaxf(a0, 0.f);
        y2s[r0 + 1][j] = fmaxf(a1, 0.f);
    }
    __syncthreads();

    // y3 = y2 @ Wc3^T + bc3
    {
        float p = y2s[warp][lane] * wc3[lane] + y2s[warp][lane + 32] * wc3[lane + 32];
        #pragma unroll
        for (int o = 16; o > 0; o >>= 1) p += __shfl_down_sync(0xffffffffu, p, o);
        if (lane == 0) out[rowBase + warp] = p + bc3[0];
    }
}

// ---------------- launch ----------------
extern "C" void kernel_launch(void* const* d_in, const int* in_sizes, int n_in,
                              void* d_out, int out_size)
{
    const void*  indices = d_in[0];
    const int*   src   = (const int*)  d_in[1];
    const int*   dst   = (const int*)  d_in[2];
    const float* w     = (const float*)d_in[3];
    const float* ndata = (const float*)d_in[4];
    const float* W1    = (const float*)d_in[5];
    const float* b1    = (const float*)d_in[6];
    const float* W2    = (const float*)d_in[7];
    const float* b2    = (const float*)d_in[8];
    const float* eps   = (const float*)d_in[9];
    const float* Wc1   = (const float*)d_in[10];
    const float* bc1   = (const float*)d_in[11];
    const float* Wc2   = (const float*)d_in[12];
    const float* bc2   = (const float*)d_in[13];
    const float* Wc3   = (const float*)d_in[14];
    const float* bc3   = (const float*)d_in[15];
    float* out = (float*)d_out;

    (void)in_sizes; (void)n_in; (void)out_size;

    int nbScan = (NN + 511) / 512;

    k_detect<<<1, 1>>>(indices);
    k_zero2<<<(NN + 255) / 256, 256>>>();
    k_deg<<<(EE + 255) / 256, 256>>>(dst);
    k_scan1<<<nbScan, 512>>>();
    k_scan2<<<1, 256>>>(nbScan);
    k_scan3<<<nbScan, 512>>>();
    k_csr<<<(EE + 255) / 256, 256>>>(src, dst, w);

    k_transpose<<<(128 * 128 + 255) / 256, 256>>>(W1, 128, 128, 0);
    k_transpose<<<(128 * 128 + 255) / 256, 256>>>(W2, 128, 128, 1);
    k_transpose<<<(128 * 384 + 255) / 256, 256>>>(Wc1, 128, 384, 2);
    k_transpose<<<( 64 * 128 + 255) / 256, 256>>>(Wc2,  64, 128, 3);

    k_layer<<<NN / 32, 256>>>(ndata, b1, eps, 0);
    k_layer<<<NN / 32, 256>>>(ndata, b2, eps, 1);

    k_head<<<BB / 8, 256>>>(indices, bc1, bc2, Wc3, bc3, out);
}

// round 8
// speedup vs baseline: 1.2543x; 1.2543x over previous
#include <cuda_runtime.h>
#include <cstdint>

#define NN  100000
#define EE  1600000
#define HD  128
#define BB  4096
#define NCTX 20

#define TILE_M 64
#define NTILES ((NN + TILE_M - 1) / TILE_M)   // 1563
#define HSTR 132
#define WSTR 132
#define SMEM_DYN ((TILE_M * HSTR + HD * WSTR) * 4)   // 101376 B -> 2 blocks/SM

// ---------------- scratch ----------------
__device__ int   g_deg[NN];
__device__ int   g_off[NN + 1];
__device__ int   g_cur[NN];
__device__ int2  g_csr_e[EE];          // (src, w bits)
__device__ float g_x1[NN * HD];
__device__ float g_x2[NN * HD];
__device__ float g_WcT1[384 * 128];
__device__ float g_WcT2[128 * 64];
__device__ int   g_part[256];
__device__ int   g_idx_is64;

// ---------------- helpers ----------------
__device__ __forceinline__ uint32_t f2tf32(float v) {
    uint32_t r;
    asm("cvt.rna.tf32.f32 %0, %1;" : "=r"(r) : "f"(v));
    return r;
}
// d += A(16x8 tf32) * B(8x8 tf32), fp32 accum, in-place
__device__ __forceinline__ void mma8(float* d, const uint32_t* a, uint32_t b0, uint32_t b1) {
    asm volatile(
        "mma.sync.aligned.m16n8k8.row.col.f32.tf32.tf32.f32 "
        "{%0,%1,%2,%3}, {%4,%5,%6,%7}, {%8,%9}, {%0,%1,%2,%3};\n"
        : "+f"(d[0]), "+f"(d[1]), "+f"(d[2]), "+f"(d[3])
        : "r"(a[0]), "r"(a[1]), "r"(a[2]), "r"(a[3]), "r"(b0), "r"(b1));
}

// ---------------- prep: zero + detect + Wc transposes ----------------
__global__ void k_prep(const void* __restrict__ idx,
                       const float* __restrict__ Wc1, const float* __restrict__ Wc2)
{
    int b = blockIdx.x, t = threadIdx.x;
    if (b < 391) {
        int i = b * 256 + t;
        if (i < NN) { g_deg[i] = 0; g_cur[i] = 0; }
    } else if (b == 391) {
        if (t == 0) {
            const long long* p = (const long long*)idx;
            int ok = 1;
            for (int i = 0; i < 23; ++i) { long long v = p[i]; if (v < 0 || v >= NN) ok = 0; }
            g_idx_is64 = ok;
        }
    } else if (b < 584) {               // WcT1: 49152 elems
        int e = (b - 392) * 256 + t;
        int j = e / 384, k = e - j * 384;
        g_WcT1[k * 128 + j] = Wc1[e];
    } else {                            // WcT2: 8192 elems
        int e = (b - 584) * 256 + t;
        int j = e >> 7, k = e & 127;
        g_WcT2[k * 64 + j] = Wc2[e];
    }
}

// ---------------- CSR build ----------------
__global__ void k_deg(const int* __restrict__ dst) {
    int e = blockIdx.x * 256 + threadIdx.x;
    if (e < EE) {
        int d = min(max(dst[e], 0), NN - 1);
        atomicAdd(&g_deg[d], 1);
    }
}

__global__ void k_scan1() {
    __shared__ int s[512];
    int tid = threadIdx.x;
    int gid = blockIdx.x * 512 + tid;
    int v = (gid < NN) ? g_deg[gid] : 0;
    s[tid] = v; __syncthreads();
    for (int o = 1; o < 512; o <<= 1) {
        int t = (tid >= o) ? s[tid - o] : 0;
        __syncthreads();
        s[tid] += t;
        __syncthreads();
    }
    if (gid < NN) g_off[gid] = s[tid] - v;
    if (tid == 511) g_part[blockIdx.x] = s[511];
}

__global__ void k_scan3() {
    __shared__ int red[16];
    __shared__ int sOff;
    int b = blockIdx.x, tid = threadIdx.x;
    int acc = 0;
    for (int i = tid; i < b; i += 512) acc += g_part[i];
    #pragma unroll
    for (int o = 16; o > 0; o >>= 1) acc += __shfl_down_sync(0xffffffffu, acc, o);
    if ((tid & 31) == 0) red[tid >> 5] = acc;
    __syncthreads();
    if (tid == 0) {
        int s = 0;
        #pragma unroll
        for (int i = 0; i < 16; ++i) s += red[i];
        sOff = s;
    }
    __syncthreads();
    int gid = b * 512 + tid;
    if (gid < NN) g_off[gid] += sOff;
    if (b == 0 && tid == 0) g_off[NN] = EE;
}

__global__ void k_csr(const int* __restrict__ src, const int* __restrict__ dst,
                      const float* __restrict__ w) {
    int e = blockIdx.x * 256 + threadIdx.x;
    if (e < EE) {
        int d = min(max(dst[e], 0), NN - 1);
        int s = min(max(src[e], 0), NN - 1);
        int slot = g_off[d] + atomicAdd(&g_cur[d], 1);
        g_csr_e[slot] = make_int2(s, __float_as_int(w[e]));
    }
}

// ---------------- fused GIN layer: gather -> tf32 mma.sync (3xTF32) -> epilogue ----------------
// 64 nodes/block, 8 warps = 2(m-groups of 32 rows) x 4(n-groups of 32 cols)
__global__ __launch_bounds__(256, 2)
void k_layer(const float* __restrict__ ndata,
             const float* __restrict__ W,
             const float* __restrict__ b,
             const float* __restrict__ eps,
             int layer)
{
    extern __shared__ float smem[];
    float* Hs = smem;                        // [64][HSTR]
    float* Ws = smem + TILE_M * HSTR;        // [128][WSTR] raw fp32 W (row j, col k)
    __shared__ float bs[128];

    const float* xin  = layer ? g_x1 : ndata;
    float*       xout = layer ? g_x2 : g_x1;

    int tid = threadIdx.x, warp = tid >> 5, lane = tid & 31;
    int nodeBase = blockIdx.x * TILE_M;
    float epsv = 1.0f + __ldg(&eps[layer]);

    if (tid < 128) bs[tid] = b[tid];

    // copy W (64KB) into padded smem
    {
        const float4* wsrc = (const float4*)W;
        #pragma unroll
        for (int i = 0; i < 16; ++i) {
            int idx = tid + i * 256;         // 0..4095
            int r = idx >> 5, s = idx & 31;
            *(float4*)&Ws[r * WSTR + (s << 2)] = __ldg(&wsrc[idx]);
        }
    }

    // gather: each warp computes h for 8 nodes
    const float4* x4 = (const float4*)xin;
    for (int n = 0; n < 8; ++n) {
        int m = warp * 8 + n;
        int node = nodeBase + m;
        int beg = 0, end = 0;
        if (node < NN) { beg = g_off[node]; end = g_off[node + 1]; }
        float ax = 0.f, ay = 0.f, az = 0.f, aw = 0.f;
        for (int base = beg; base < end; base += 32) {
            int nrem = end - base; if (nrem > 32) nrem = 32;
            int2 ed = make_int2(0, 0);
            if (lane < nrem) ed = g_csr_e[base + lane];
            #pragma unroll 8
            for (int j = 0; j < nrem; ++j) {
                int   ss = __shfl_sync(0xffffffffu, ed.x, j);
                float ww = __int_as_float(__shfl_sync(0xffffffffu, ed.y, j));
                float4 xv = x4[ss * 32 + lane];
                ax += ww * xv.x; ay += ww * xv.y; az += ww * xv.z; aw += ww * xv.w;
            }
        }
        float4 h = make_float4(0.f, 0.f, 0.f, 0.f);
        if (node < NN) {
            float inv = 1.0f / fmaxf((float)(end - beg), 1.0f);
            float4 xi = x4[node * 32 + lane];
            h.x = epsv * xi.x + ax * inv;
            h.y = epsv * xi.y + ay * inv;
            h.z = epsv * xi.z + az * inv;
            h.w = epsv * xi.w + aw * inv;
        }
        *(float4*)&Hs[m * HSTR + (lane << 2)] = h;
    }
    __syncthreads();

    // GEMM: Out[64][128] = H[64][128] @ W^T, 3xTF32 via mma.sync
    int wm = warp >> 2;          // 0..1
    int wn = warp & 3;           // 0..3
    int g  = lane >> 2, t = lane & 3;

    float acc[2][4][4];
    #pragma unroll
    for (int mt = 0; mt < 2; ++mt)
        #pragma unroll
        for (int nt = 0; nt < 4; ++nt)
            #pragma unroll
            for (int i = 0; i < 4; ++i) acc[mt][nt][i] = 0.f;

    #pragma unroll 4
    for (int kt = 0; kt < 16; ++kt) {
        int k0 = kt * 8;
        uint32_t ah[2][4], al[2][4];
        #pragma unroll
        for (int mt = 0; mt < 2; ++mt) {
            int row = wm * 32 + mt * 16 + g;
            float v0 = Hs[row * HSTR + k0 + t];
            float v1 = Hs[(row + 8) * HSTR + k0 + t];
            float v2 = Hs[row * HSTR + k0 + t + 4];
            float v3 = Hs[(row + 8) * HSTR + k0 + t + 4];
            ah[mt][0] = f2tf32(v0); al[mt][0] = f2tf32(v0 - __uint_as_float(ah[mt][0]));
            ah[mt][1] = f2tf32(v1); al[mt][1] = f2tf32(v1 - __uint_as_float(ah[mt][1]));
            ah[mt][2] = f2tf32(v2); al[mt][2] = f2tf32(v2 - __uint_as_float(ah[mt][2]));
            ah[mt][3] = f2tf32(v3); al[mt][3] = f2tf32(v3 - __uint_as_float(ah[mt][3]));
        }
        #pragma unroll
        for (int nt = 0; nt < 4; ++nt) {
            int nj = wn * 32 + nt * 8 + g;      // output column (W row)
            float bv0 = Ws[nj * WSTR + k0 + t];
            float bv1 = Ws[nj * WSTR + k0 + t + 4];
            uint32_t bh0 = f2tf32(bv0), bh1 = f2tf32(bv1);
            uint32_t bl0 = f2tf32(bv0 - __uint_as_float(bh0));
            uint32_t bl1 = f2tf32(bv1 - __uint_as_float(bh1));
            #pragma unroll
            for (int mt = 0; mt < 2; ++mt) {
                mma8(acc[mt][nt], ah[mt], bh0, bh1);
                mma8(acc[mt][nt], al[mt], bh0, bh1);
                mma8(acc[mt][nt], ah[mt], bl0, bl1);
            }
        }
    }

    // epilogue: bias + activation + store
    #pragma unroll
    for (int mt = 0; mt < 2; ++mt) {
        int node0 = nodeBase + wm * 32 + mt * 16 + g;
        #pragma unroll
        for (int nt = 0; nt < 4; ++nt) {
            int col = wn * 32 + nt * 8 + (t << 1);
            float b0 = bs[col], b1 = bs[col + 1];
            float v00 = acc[mt][nt][0] + b0, v01 = acc[mt][nt][1] + b1;
            float v10 = acc[mt][nt][2] + b0, v11 = acc[mt][nt][3] + b1;
            if (layer == 0) {
                v00 = fmaxf(v00, 0.f); v01 = fmaxf(v01, 0.f);
                v10 = fmaxf(v10, 0.f); v11 = fmaxf(v11, 0.f);
            } else if (node0 == 0) {
                v00 = 0.f; v01 = 0.f;
            }
            if (node0 < NN)     *(float2*)(xout + node0 * 128 + col)       = make_float2(v00, v01);
            if (node0 + 8 < NN) *(float2*)(xout + (node0 + 8) * 128 + col) = make_float2(v10, v11);
        }
    }
}

// ---------------- head MLP: 8 rows per block, dual-dtype index gather ----------------
__global__ __launch_bounds__(256) void k_head(const void* __restrict__ idxp,
                                              const float* __restrict__ bc1,
                                              const float* __restrict__ bc2,
                                              const float* __restrict__ wc3,
                                              const float* __restrict__ bc3,
                                              float* __restrict__ out)
{
    __shared__ float fs [8][384];
    __shared__ float y1s[8][128];
    __shared__ float y2s[8][64];
    int tid = threadIdx.x, warp = tid >> 5, lane = tid & 31;
    int rowBase = blockIdx.x << 3;

    {
        int row = rowBase + warp;
        int i1, i2, cnt = 0;
        int ctxi[NCTX];
        if (g_idx_is64) {
            const long long* ip = (const long long*)idxp + (long long)row * 23;
            i1 = (int)ip[0]; i2 = (int)ip[1];
            #pragma unroll
            for (int t = 0; t < NCTX; ++t) {
                long long cl = ip[3 + t];
                ctxi[t] = min(max((int)cl, 0), NN - 1);
                if (cl > 0) cnt++;
            }
        } else {
            const int* ip = (const int*)idxp + row * 23;
            i1 = ip[0]; i2 = ip[1];
            #pragma unroll
            for (int t = 0; t < NCTX; ++t) {
                int ci = ip[3 + t];
                ctxi[t] = min(max(ci, 0), NN - 1);
                if (ci > 0) cnt++;
            }
        }
        i1 = min(max(i1, 0), NN - 1);
        i2 = min(max(i2, 0), NN - 1);

        const float4* x4 = (const float4*)g_x2;
        *(float4*)&fs[warp][lane << 2]         = x4[i1 * 32 + lane];
        *(float4*)&fs[warp][128 + (lane << 2)] = x4[i2 * 32 + lane];
        float sx = 0.f, sy = 0.f, sz = 0.f, sw = 0.f;
        #pragma unroll 4
        for (int t = 0; t < NCTX; ++t) {
            float4 xv = x4[ctxi[t] * 32 + lane];
            sx += xv.x; sy += xv.y; sz += xv.z; sw += xv.w;
        }
        float inv = 1.0f / (float)(cnt > 0 ? cnt : 1);
        float4 cv; cv.x = sx * inv; cv.y = sy * inv; cv.z = sz * inv; cv.w = sw * inv;
        *(float4*)&fs[warp][256 + (lane << 2)] = cv;
    }
    __syncthreads();

    {
        int j  = tid & 127;
        int r0 = (tid >> 7) << 2;
        float a0 = bc1[j], a1 = a0, a2 = a0, a3 = a0;
        #pragma unroll 4
        for (int k = 0; k < 384; ++k) {
            float wv = g_WcT1[k * 128 + j];
            a0 += fs[r0 + 0][k] * wv;
            a1 += fs[r0 + 1][k] * wv;
            a2 += fs[r0 + 2][k] * wv;
            a3 += fs[r0 + 3][k] * wv;
        }
        y1s[r0 + 0][j] = fmaxf(a0, 0.f);
        y1s[r0 + 1][j] = fmaxf(a1, 0.f);
        y1s[r0 + 2][j] = fmaxf(a2, 0.f);
        y1s[r0 + 3][j] = fmaxf(a3, 0.f);
    }
    __syncthreads();

    {
        int j  = tid & 63;
        int r0 = (tid >> 6) << 1;
        float a0 = bc2[j], a1 = a0;
        #pragma unroll 4
        for (int k = 0; k < 128; ++k) {
            float wv = g_WcT2[k * 64 + j];
            a0 += y1s[r0 + 0][k] * wv;
            a1 += y1s[r0 + 1][k] * wv;
        }
        y2s[r0 + 0][j] = fmaxf(a0, 0.f);
        y2s[r0 + 1][j] = fmaxf(a1, 0.f);
    }
    __syncthreads();

    {
        float p = y2s[warp][lane] * wc3[lane] + y2s[warp][lane + 32] * wc3[lane + 32];
        #pragma unroll
        for (int o = 16; o > 0; o >>= 1) p += __shfl_down_sync(0xffffffffu, p, o);
        if (lane == 0) out[rowBase + warp] = p + bc3[0];
    }
}

// ---------------- launch ----------------
extern "C" void kernel_launch(void* const* d_in, const int* in_sizes, int n_in,
                              void* d_out, int out_size)
{
    const void*  indices = d_in[0];
    const int*   src   = (const int*)  d_in[1];
    const int*   dst   = (const int*)  d_in[2];
    const float* w     = (const float*)d_in[3];
    const float* ndata = (const float*)d_in[4];
    const float* W1    = (const float*)d_in[5];
    const float* b1    = (const float*)d_in[6];
    const float* W2    = (const float*)d_in[7];
    const float* b2    = (const float*)d_in[8];
    const float* eps   = (const float*)d_in[9];
    const float* Wc1   = (const float*)d_in[10];
    const float* bc1   = (const float*)d_in[11];
    const float* Wc2   = (const float*)d_in[12];
    const float* bc2   = (const float*)d_in[13];
    const float* Wc3   = (const float*)d_in[14];
    const float* bc3   = (const float*)d_in[15];
    float* out = (float*)d_out;

    (void)in_sizes; (void)n_in; (void)out_size;

    static bool s_attr = false;
    if (!s_attr) {
        cudaFuncSetAttribute(k_layer, cudaFuncAttributeMaxDynamicSharedMemorySize, SMEM_DYN);
        s_attr = true;
    }

    int nbScan = (NN + 511) / 512;

    k_prep <<<616, 256>>>(indices, Wc1, Wc2);
    k_deg  <<<(EE + 255) / 256, 256>>>(dst);
    k_scan1<<<nbScan, 512>>>();
    k_scan3<<<nbScan, 512>>>();
    k_csr  <<<(EE + 255) / 256, 256>>>(src, dst, w);

    k_layer<<<NTILES, 256, SMEM_DYN>>>(ndata, W1, b1, eps, 0);
    k_layer<<<NTILES, 256, SMEM_DYN>>>(ndata, W2, b2, eps, 1);

    k_head <<<BB / 8, 256>>>(indices, bc1, bc2, Wc3, bc3, out);
}